// round 11
// baseline (speedup 1.0000x reference)
#include <cuda_runtime.h>
#include <cstdint>

#define N_DIST 1024
#define DIM    128
#define HID    256
#define MAXN   500000
#define NBLK   512
#define PROWS  16            // rows per pipeline stage
#define RSTAGE 4             // ring stages
#define ROWB   512           // bytes per x row (128 fp32)
#define IDXBUF 1024

// Scratch (no allocations allowed) — fully rewritten every launch.
__device__ int   g_counts[N_DIST * NBLK];   // [d][b]
__device__ int   g_bcursor[NBLK * N_DIST];  // [b][d]
__device__ int   g_total[N_DIST];
__device__ int   g_offsets[N_DIST + 1];
__device__ int   g_order[MAXN];
__device__ float g_head[N_DIST * DIM];
__device__ int   g_done[N_DIST / 8];

// ---------------------------------------------------------------- PTX helpers
__device__ __forceinline__ uint32_t smem_u32(const void* p) {
    uint32_t a;
    asm("{ .reg .u64 t; cvta.to.shared.u64 t, %1; cvt.u32.u64 %0, t; }" : "=r"(a) : "l"(p));
    return a;
}
#define MBAR_INIT(a, c) \
    asm volatile("mbarrier.init.shared.b64 [%0], %1;" :: "r"(a), "r"(c) : "memory")
#define MBAR_EXPECT_TX(a, b) \
    asm volatile("mbarrier.arrive.expect_tx.shared.b64 _, [%0], %1;" :: "r"(a), "r"(b) : "memory")
#define MBAR_ARRIVE(a) \
    asm volatile("mbarrier.arrive.shared.b64 _, [%0];" :: "r"(a) : "memory")
#define MBAR_WAIT(a, p) do {                                                       \
    uint32_t _m = (a), _p = (p), _d;                                               \
    asm volatile("{\n\t.reg .pred P;\n\t"                                          \
        "mbarrier.try_wait.parity.acquire.cta.shared::cta.b64 P, [%1], %2;\n\t"    \
        "selp.b32 %0,1,0,P;\n\t}" : "=r"(_d) : "r"(_m), "r"(_p) : "memory");       \
    if (!_d) {                                                                     \
        asm volatile("{\n\t.reg .pred P;\n"                                        \
            "LW%=:\n\t"                                                            \
            "mbarrier.try_wait.parity.acquire.cta.shared::cta.b64 P, [%0], %1, 0x989680;\n\t" \
            "@P bra LD%=;\n\t"                                                     \
            "bra LW%=;\n"                                                          \
            "LD%=:\n\t}" :: "r"(_m), "r"(_p) : "memory");                          \
    } } while (0)
#define BULK_G2S(dst, src, bytes, mbar) \
    asm volatile("cp.async.bulk.shared::cta.global.mbarrier::complete_tx::bytes [%0], [%1], %2, [%3];" \
        :: "r"(dst), "l"(src), "r"(bytes), "r"(mbar) : "memory")

// ---------------------------------------------------------------- A: per-block histogram
__global__ void __launch_bounds__(256) k_hist(const int4* __restrict__ zone4, int n4, int chunk4) {
    __shared__ int sh[N_DIST];
    int b = blockIdx.x, t = threadIdx.x;
    if (b == 0 && t < N_DIST / 8) g_done[t] = 0;     // reset completion counters each launch
    for (int i = t; i < N_DIST; i += 256) sh[i] = 0;
    __syncthreads();
    int s = b * chunk4, e = min(n4, s + chunk4);
    for (int i = s + t; i < e; i += 256) {
        int4 z = zone4[i];
        atomicAdd(&sh[z.x], 1);
        atomicAdd(&sh[z.y], 1);
        atomicAdd(&sh[z.z], 1);
        atomicAdd(&sh[z.w], 1);
    }
    __syncthreads();
    for (int i = t; i < N_DIST; i += 256)
        g_counts[i * NBLK + b] = sh[i];              // strided write (hidden)
}

// ---------------------------------------------------------------- B: scan over blocks per district
__global__ void __launch_bounds__(NBLK) k_scan_blocks() {
    __shared__ int s[NBLK];
    int d = blockIdx.x, t = threadIdx.x;
    int c = g_counts[d * NBLK + t];                  // coalesced read
    s[t] = c;
    __syncthreads();
    for (int off = 1; off < NBLK; off <<= 1) {
        int add = (t >= off) ? s[t - off] : 0;
        __syncthreads();
        s[t] += add;
        __syncthreads();
    }
    g_bcursor[t * N_DIST + d] = s[t] - c;            // strided write (hidden)
    if (t == NBLK - 1) g_total[d] = s[t];
}

// ---------------------------------------------------------------- C: scatter (inline district scan + smem atomics)
__global__ void __launch_bounds__(256) k_scatter(const int4* __restrict__ zone4, int n4, int chunk4) {
    __shared__ int cur[N_DIST];
    __shared__ int warp_part[8];
    int b = blockIdx.x, t = threadIdx.x;
    int lane = t & 31, w = t >> 5;

    // --- inline exclusive scan of g_total (1024 elems, 4 per thread) ---
    int4 tt = ((const int4*)g_total)[t];
    int mysum = tt.x + tt.y + tt.z + tt.w;
    int inc = mysum;
    #pragma unroll
    for (int o = 1; o < 32; o <<= 1) {
        int v = __shfl_up_sync(0xffffffffu, inc, o);
        if (lane >= o) inc += v;
    }
    if (lane == 31) warp_part[w] = inc;
    __syncthreads();
    if (t == 0) {
        int run = 0;
        #pragma unroll
        for (int i = 0; i < 8; i++) { int v = warp_part[i]; warp_part[i] = run; run += v; }
    }
    __syncthreads();
    int e0 = warp_part[w] + (inc - mysum);
    int e1 = e0 + tt.x, e2 = e1 + tt.y, e3 = e2 + tt.z;

    if (b == 0) {                                     // publish offsets for gather
        g_offsets[4 * t + 0] = e0;
        g_offsets[4 * t + 1] = e1;
        g_offsets[4 * t + 2] = e2;
        g_offsets[4 * t + 3] = e3;
        if (t == 255) g_offsets[N_DIST] = e3 + tt.w;
    }

    int4 bc = ((const int4*)g_bcursor)[b * (N_DIST / 4) + t];   // coalesced
    cur[4 * t + 0] = e0 + bc.x;
    cur[4 * t + 1] = e1 + bc.y;
    cur[4 * t + 2] = e2 + bc.z;
    cur[4 * t + 3] = e3 + bc.w;
    __syncthreads();

    int s = b * chunk4, e = min(n4, s + chunk4);
    for (int i = s + t; i < e; i += 256) {
        int4 z = zone4[i];
        int p0 = atomicAdd(&cur[z.x], 1);
        int p1 = atomicAdd(&cur[z.y], 1);
        int p2 = atomicAdd(&cur[z.z], 1);
        int p3 = atomicAdd(&cur[z.w], 1);
        int i0 = i * 4;
        g_order[p0] = i0;
        g_order[p1] = i0 + 1;
        g_order[p2] = i0 + 2;
        g_order[p3] = i0 + 3;
    }
}

// ---------------------------------------------------------------- D: gather (bulk-copy pipeline) + fused MLP
// 1024 blocks (one per district), 288 threads = 8 consumer warps + 1 producer warp.
// Producer issues cp.async.bulk 512B row copies into a 4-stage x 16-row smem ring;
// consumers sum rows from smem. Last-finishing block of each 8-district group runs the MLP.
__global__ void __launch_bounds__(288) k_gather(
    const float* __restrict__ xf,
    const float* __restrict__ w1, const float* __restrict__ b1,
    const float* __restrict__ w2, const float* __restrict__ b2,
    float* __restrict__ out)
{
    __shared__ __align__(16) char ring[RSTAGE * PROWS * ROWB];   // 32KB, reused by MLP
    __shared__ int    sh_idx[IDXBUF];
    __shared__ float4 sh_part[8][32];
    __shared__ __align__(8) unsigned long long mb_full[RSTAGE], mb_empty[RSTAGE];
    __shared__ int sh_last;

    int d = blockIdx.x, t = threadIdx.x;
    int w = t >> 5, lane = t & 31;
    int s = g_offsets[d];
    int cntF = g_offsets[d + 1] - s;

    if (t == 0) {
        #pragma unroll
        for (int i = 0; i < RSTAGE; i++) {
            MBAR_INIT(smem_u32(&mb_full[i]), 1);     // expect_tx arrive
            MBAR_INIT(smem_u32(&mb_empty[i]), 8);    // one arrive per consumer warp
        }
    }
    uint32_t ring0 = smem_u32(ring);
    float4 acc = make_float4(0.f, 0.f, 0.f, 0.f);
    int st = 0, ph_p = 1, ph_c = 0;                  // producer starts phase 1 (first empty-wait passes)

    for (int off = 0; off < cntF; off += IDXBUF) {
        int cnt = min(IDXBUF, cntF - off);
        __syncthreads();
        for (int i = t; i < cnt; i += 288)
            sh_idx[i] = g_order[s + off + i];
        __syncthreads();
        int nstage = (cnt + PROWS - 1) / PROWS;

        if (w == 8) {
            // -------- producer warp --------
            for (int sg = 0; sg < nstage; sg++) {
                uint32_t fb = smem_u32(&mb_full[st]);
                MBAR_WAIT(smem_u32(&mb_empty[st]), ph_p);
                int rbase = sg * PROWS;
                int rows = min(PROWS, cnt - rbase);
                if (lane == 0) MBAR_EXPECT_TX(fb, rows * ROWB);
                __syncwarp();
                if (lane < rows) {
                    const char* src = (const char*)xf + (size_t)sh_idx[rbase + lane] * ROWB;
                    BULK_G2S(ring0 + (st * PROWS + lane) * ROWB, src, ROWB, fb);
                }
                if (++st == RSTAGE) { st = 0; ph_p ^= 1; }
            }
        } else {
            // -------- consumer warps (w 0..7): 2 rows per warp per stage --------
            for (int sg = 0; sg < nstage; sg++) {
                MBAR_WAIT(smem_u32(&mb_full[st]), ph_c);
                int rbase = sg * PROWS;
                int rows = min(PROWS, cnt - rbase);
                #pragma unroll
                for (int rr = 0; rr < 2; rr++) {
                    int j = w * 2 + rr;
                    if (j < rows) {
                        float4 v = *(const float4*)(ring + (st * PROWS + j) * ROWB + lane * 16);
                        acc.x += v.x; acc.y += v.y; acc.z += v.z; acc.w += v.w;
                    }
                }
                __syncwarp();
                if (lane == 0) MBAR_ARRIVE(smem_u32(&mb_empty[st]));
                if (++st == RSTAGE) { st = 0; ph_c ^= 1; }
            }
        }
    }

    if (w < 8) sh_part[w][lane] = acc;
    __syncthreads();
    if (w == 0) {
        float4 r = sh_part[0][lane];
        #pragma unroll
        for (int wi = 1; wi < 8; wi++) {
            float4 p = sh_part[wi][lane];
            r.x += p.x; r.y += p.y; r.z += p.z; r.w += p.w;
        }
        ((float4*)g_head)[d * 32 + lane] = r;        // full district sum (pre-ReLU)
        __threadfence();
    }
    __syncthreads();

    int grp = d >> 3;
    if (t == 0) sh_last = (atomicAdd(&g_done[grp], 1) == 7) ? 1 : 0;
    __syncthreads();
    if (!sh_last) return;

    // ---------------- fused MLP for this group's 8 districts ----------------
    int base = grp * 8;
    float (*sh_head)[DIM] = (float(*)[DIM])ring;             // 4KB over ring
    float (*sh_h1)[HID]   = (float(*)[HID])(ring + 4096);    // 8KB over ring
    __syncthreads();                                         // ring fully consumed
    for (int idx = t; idx < 8 * DIM; idx += 288)
        sh_head[idx >> 7][idx & 127] = fmaxf(__ldcg(&g_head[base * DIM + idx]), 0.f);
    __syncthreads();

    if (t < 256) {                                   // Phase A: h1 = relu(head @ w1 + b1)
        int col = t;
        float accm[8];
        float bb = b1[col];
        #pragma unroll
        for (int r = 0; r < 8; r++) accm[r] = bb;
        #pragma unroll 4
        for (int k = 0; k < DIM; k++) {
            float wv = w1[k * HID + col];
            #pragma unroll
            for (int r = 0; r < 8; r++) accm[r] += sh_head[r][k] * wv;
        }
        #pragma unroll
        for (int r = 0; r < 8; r++) sh_h1[r][col] = fmaxf(accm[r], 0.f);
    }
    __syncthreads();

    if (t < 256) {                                   // Phase B: out = h1 @ w2 + b2
        int col = t & 127;
        int r0  = (t >> 7) * 4;
        float accm[4];
        float bb = b2[col];
        #pragma unroll
        for (int r = 0; r < 4; r++) accm[r] = bb;
        #pragma unroll 4
        for (int k = 0; k < HID; k++) {
            float wv = w2[k * DIM + col];
            #pragma unroll
            for (int r = 0; r < 4; r++) accm[r] += sh_h1[r0 + r][k] * wv;
        }
        #pragma unroll
        for (int r = 0; r < 4; r++)
            out[(size_t)(base + r0 + r) * DIM + col] = accm[r];
    }
}

// ---------------------------------------------------------------- launch
extern "C" void kernel_launch(void* const* d_in, const int* in_sizes, int n_in,
                              void* d_out, int out_size) {
    const float* x    = (const float*)d_in[0];
    const int*   zone = (const int*)d_in[1];
    const float* w1   = (const float*)d_in[2];
    const float* b1   = (const float*)d_in[3];
    const float* w2   = (const float*)d_in[4];
    const float* b2   = (const float*)d_in[5];
    float*       out  = (float*)d_out;
    int n  = in_sizes[1];                // 500000, divisible by 4
    int n4 = n / 4;
    int chunk4 = (n4 + NBLK - 1) / NBLK;

    k_hist       <<<NBLK, 256>>>((const int4*)zone, n4, chunk4);
    k_scan_blocks<<<N_DIST, NBLK>>>();
    k_scatter    <<<NBLK, 256>>>((const int4*)zone, n4, chunk4);
    k_gather     <<<N_DIST, 288>>>(x, w1, b1, w2, b2, out);
}

// round 13
// speedup vs baseline: 1.0007x; 1.0007x over previous
#include <cuda_runtime.h>
#include <cstdint>

#define N_DIST 1024
#define DIM    128
#define HID    256
#define MAXN   500000
#define NBIN   512
#define GRID   (N_DIST * 2)
#define GCHUNK 2048

// Scratch (no allocations). Counters are epoch-relative monotonic: never reset.
__device__ __align__(16) int g_counts[N_DIST * NBIN];   // [d][b]
__device__ __align__(16) int g_bcursor[NBIN * N_DIST];  // [b][d]
__device__ __align__(16) int g_total[N_DIST];
__device__ __align__(16) int g_offsets[N_DIST + 1];
__device__ int   g_order[MAXN];
__device__ float g_heads[2][N_DIST * DIM];
__device__ int   g_done[N_DIST / 8];   // +16 per group per launch
__device__ int   g_bar[4];             // +NBIN per launch each
__device__ int   g_grpdone;            // +128 per launch
__device__ int   g_epoch;              // launch counter

__device__ __forceinline__ void grid_bar(int k, int E, int t) {
    __syncthreads();
    if (t == 0) {
        __threadfence();
        atomicAdd(&g_bar[k], 1);
        while (*(volatile int*)&g_bar[k] < (E + 1) * NBIN) __nanosleep(128);
        __threadfence();
    }
    __syncthreads();
}

__global__ void __launch_bounds__(256, 4) k_all(
    const int4* __restrict__ zone4, int n4, int chunk4,
    const float4* __restrict__ x4,
    const float* __restrict__ w1, const float* __restrict__ b1,
    const float* __restrict__ w2, const float* __restrict__ b2,
    float* __restrict__ out)
{
    __shared__ __align__(16) char buf[12 * 1024];   // hist table / cur / sh_idx / MLP tiles
    __shared__ float4 sh_part[8][32];
    __shared__ int warp_part[8];
    __shared__ int sh_tmp;

    int bid = blockIdx.x, t = threadIdx.x;
    int lane = t & 31, w = t >> 5;

    if (t == 0) sh_tmp = *(volatile int*)&g_epoch;
    __syncthreads();
    int E = sh_tmp;

    if (bid < NBIN) {
        // ================= P1: per-block histogram =================
        int* sh = (int*)buf;
        for (int i = t; i < N_DIST; i += 256) sh[i] = 0;
        __syncthreads();
        int s = bid * chunk4, e = min(n4, s + chunk4);
        for (int i = s + t; i < e; i += 256) {
            int4 z = zone4[i];
            atomicAdd(&sh[z.x], 1); atomicAdd(&sh[z.y], 1);
            atomicAdd(&sh[z.z], 1); atomicAdd(&sh[z.w], 1);
        }
        __syncthreads();
        for (int i = t; i < N_DIST; i += 256)
            g_counts[i * NBIN + bid] = sh[i];
        grid_bar(0, E, t);

        // ================= P2: per-district scan over blocks (2 districts/block) =================
        for (int dd = 0; dd < 2; dd++) {
            int d = bid * 2 + dd;
            int v0 = g_counts[d * NBIN + 2 * t];
            int v1 = g_counts[d * NBIN + 2 * t + 1];
            int ps = v0 + v1;
            int inc = ps;
            #pragma unroll
            for (int o = 1; o < 32; o <<= 1) {
                int u = __shfl_up_sync(0xffffffffu, inc, o);
                if (lane >= o) inc += u;
            }
            if (lane == 31) warp_part[w] = inc;
            __syncthreads();
            if (t == 0) {
                int run = 0;
                #pragma unroll
                for (int i = 0; i < 8; i++) { int v = warp_part[i]; warp_part[i] = run; run += v; }
            }
            __syncthreads();
            int epr = warp_part[w] + (inc - ps);
            g_bcursor[(2 * t) * N_DIST + d]     = epr;
            g_bcursor[(2 * t + 1) * N_DIST + d] = epr + v0;
            if (t == 255) g_total[d] = epr + ps;
            __syncthreads();
        }
        grid_bar(1, E, t);

        // ================= P3: district scan (block 0 only) =================
        if (bid == 0) {
            int4 tt = ((const int4*)g_total)[t];
            int mysum = tt.x + tt.y + tt.z + tt.w;
            int inc = mysum;
            #pragma unroll
            for (int o = 1; o < 32; o <<= 1) {
                int u = __shfl_up_sync(0xffffffffu, inc, o);
                if (lane >= o) inc += u;
            }
            if (lane == 31) warp_part[w] = inc;
            __syncthreads();
            if (t == 0) {
                int run = 0;
                #pragma unroll
                for (int i = 0; i < 8; i++) { int v = warp_part[i]; warp_part[i] = run; run += v; }
            }
            __syncthreads();
            int e0 = warp_part[w] + (inc - mysum);
            g_offsets[4 * t + 0] = e0;
            g_offsets[4 * t + 1] = e0 + tt.x;
            g_offsets[4 * t + 2] = e0 + tt.x + tt.y;
            g_offsets[4 * t + 3] = e0 + tt.x + tt.y + tt.z;
            if (t == 255) g_offsets[N_DIST] = e0 + mysum;
        }
        grid_bar(2, E, t);

        // ================= P4: scatter (smem atomics) =================
        int* cur = (int*)buf;
        int4 off = ((const int4*)g_offsets)[t];
        int4 bc  = ((const int4*)g_bcursor)[bid * (N_DIST / 4) + t];
        cur[4 * t + 0] = off.x + bc.x;
        cur[4 * t + 1] = off.y + bc.y;
        cur[4 * t + 2] = off.z + bc.z;
        cur[4 * t + 3] = off.w + bc.w;
        __syncthreads();
        for (int i = s + t; i < e; i += 256) {
            int4 z = zone4[i];
            int p0 = atomicAdd(&cur[z.x], 1);
            int p1 = atomicAdd(&cur[z.y], 1);
            int p2 = atomicAdd(&cur[z.z], 1);
            int p3 = atomicAdd(&cur[z.w], 1);
            int i0 = i * 4;
            g_order[p0] = i0;
            g_order[p1] = i0 + 1;
            g_order[p2] = i0 + 2;
            g_order[p3] = i0 + 3;
        }
        grid_bar(3, E, t);
    } else {
        // Late blocks: wait for binning release (in practice already set)
        if (t == 0) {
            while (*(volatile int*)&g_bar[3] < (E + 1) * NBIN) __nanosleep(256);
        }
        __syncthreads();
        __threadfence();
    }

    // ================= gather (split-2, all 2048 blocks) =================
    int d = bid >> 1, h = bid & 1;
    int s0 = g_offsets[d], e0g = g_offsets[d + 1];
    int cnt0 = e0g - s0;
    int half = (cnt0 + 1) >> 1;
    int sg = s0 + (h ? half : 0);
    int eg = h ? e0g : (s0 + half);
    int cnt = eg - sg;
    int* sh_idx = (int*)buf;
    float4 acc = make_float4(0.f, 0.f, 0.f, 0.f);

    for (int base = 0; base < cnt; base += GCHUNK) {
        int m = min(GCHUNK, cnt - base);
        __syncthreads();
        for (int i = t; i < m; i += 256)
            sh_idx[i] = g_order[sg + base + i];
        __syncthreads();

        int r = w;
        for (; r + 64 <= m; r += 64) {
            float4 v[8];
            #pragma unroll
            for (int u = 0; u < 8; u++) {
                size_t p = (size_t)sh_idx[r + u * 8] * 32 + lane;
                v[u] = __ldcs(&x4[p]);
            }
            #pragma unroll
            for (int u = 0; u < 8; u++) {
                acc.x += v[u].x; acc.y += v[u].y;
                acc.z += v[u].z; acc.w += v[u].w;
            }
        }
        for (; r < m; r += 8) {
            float4 v = __ldcs(&x4[(size_t)sh_idx[r] * 32 + lane]);
            acc.x += v.x; acc.y += v.y; acc.z += v.z; acc.w += v.w;
        }
    }

    sh_part[w][lane] = acc;
    __syncthreads();
    if (w == 0) {
        float4 r = sh_part[0][lane];
        #pragma unroll
        for (int wi = 1; wi < 8; wi++) {
            float4 p = sh_part[wi][lane];
            r.x += p.x; r.y += p.y; r.z += p.z; r.w += p.w;
        }
        ((float4*)g_heads[h])[d * 32 + lane] = r;
        __threadfence();
    }
    __syncthreads();

    int grp = d >> 3;
    if (t == 0) {
        int old = atomicAdd(&g_done[grp], 1);
        sh_tmp = (old == (E + 1) * 16 - 1) ? 1 : 0;
    }
    __syncthreads();
    if (!sh_tmp) return;
    __threadfence();

    // ================= fused MLP for this group's 8 districts =================
    int gbase = grp * 8;
    float (*sh_head)[DIM] = (float(*)[DIM])buf;            // 4KB
    float (*sh_h1)[HID]   = (float(*)[HID])(buf + 4096);   // 8KB
    for (int idx = t; idx < 8 * DIM; idx += 256) {
        float p = __ldcg(&g_heads[0][gbase * DIM + idx]) + __ldcg(&g_heads[1][gbase * DIM + idx]);
        sh_head[idx >> 7][idx & 127] = fmaxf(p, 0.f);
    }
    __syncthreads();

    {   // Phase A: h1 = relu(head @ w1 + b1)
        int col = t;
        float accm[8];
        float bb = b1[col];
        #pragma unroll
        for (int r = 0; r < 8; r++) accm[r] = bb;
        #pragma unroll 4
        for (int k = 0; k < DIM; k++) {
            float wv = w1[k * HID + col];
            #pragma unroll
            for (int r = 0; r < 8; r++) accm[r] += sh_head[r][k] * wv;
        }
        #pragma unroll
        for (int r = 0; r < 8; r++) sh_h1[r][col] = fmaxf(accm[r], 0.f);
    }
    __syncthreads();

    {   // Phase B: out = h1 @ w2 + b2
        int col = t & 127;
        int r0  = (t >> 7) * 4;
        float accm[4];
        float bb = b2[col];
        #pragma unroll
        for (int r = 0; r < 4; r++) accm[r] = bb;
        #pragma unroll 4
        for (int k = 0; k < HID; k++) {
            float wv = w2[k * DIM + col];
            #pragma unroll
            for (int r = 0; r < 4; r++) accm[r] += sh_h1[r0 + r][k] * wv;
        }
        #pragma unroll
        for (int r = 0; r < 4; r++)
            out[(size_t)(gbase + r0 + r) * DIM + col] = accm[r];
    }

    __threadfence();
    if (t == 0) {
        int old = atomicAdd(&g_grpdone, 1);
        if (old == (E + 1) * 128 - 1) atomicExch(&g_epoch, E + 1);
    }
}

// ---------------------------------------------------------------- launch
extern "C" void kernel_launch(void* const* d_in, const int* in_sizes, int n_in,
                              void* d_out, int out_size) {
    const float* x    = (const float*)d_in[0];
    const int*   zone = (const int*)d_in[1];
    const float* w1   = (const float*)d_in[2];
    const float* b1   = (const float*)d_in[3];
    const float* w2   = (const float*)d_in[4];
    const float* b2   = (const float*)d_in[5];
    float*       out  = (float*)d_out;
    int n  = in_sizes[1];                // 500000, divisible by 4
    int n4 = n / 4;
    int chunk4 = (n4 + NBIN - 1) / NBIN;

    k_all<<<GRID, 256>>>((const int4*)zone, n4, chunk4, (const float4*)x,
                         w1, b1, w2, b2, out);
}

// round 14
// speedup vs baseline: 1.0406x; 1.0399x over previous
#include <cuda_runtime.h>
#include <cstdint>

#define N_DIST 1024
#define DIM    128
#define HID    256
#define MAXN   500000
#define NBIN   512
#define GCHUNK 2048
#define NGROUP (N_DIST / 8)

// Scratch (no allocations). All cross-launch counters are epoch-relative monotonic.
__device__ __align__(16) int g_counts[N_DIST * NBIN];   // [d][b]
__device__ __align__(16) int g_bcursor[NBIN * N_DIST];  // [b][d]
__device__ __align__(16) int g_total[N_DIST];
__device__ __align__(16) int g_offsets[N_DIST + 1];
__device__ int   g_order[MAXN];
__device__ float g_heads[2][N_DIST * DIM];
__device__ int   g_done[NGROUP];       // +16 per group per launch (monotonic)
__device__ int   g_bar[3];             // +NBIN per launch each (monotonic)
__device__ int   g_grpdone;            // +NGROUP per launch (monotonic)
__device__ int   g_epoch;              // bumped once per launch by last MLP group

__device__ __forceinline__ void grid_bar(int k, int E, int t) {
    __syncthreads();
    if (t == 0) {
        __threadfence();
        atomicAdd(&g_bar[k], 1);
        while (*(volatile int*)&g_bar[k] < (E + 1) * NBIN) __nanosleep(64);
        __threadfence();
    }
    __syncthreads();
}

// ================================================================ binning megakernel
// 512 blocks (all resident), 256 threads. hist -> block-scan -> district-scan -> scatter.
__global__ void __launch_bounds__(256) k_bin(const int4* __restrict__ zone4, int n4, int chunk4) {
    __shared__ int sh[N_DIST];
    __shared__ int warp_part[8];
    __shared__ int sh_e;
    int bid = blockIdx.x, t = threadIdx.x;
    int lane = t & 31, w = t >> 5;

    if (t == 0) sh_e = *(volatile int*)&g_epoch;
    for (int i = t; i < N_DIST; i += 256) sh[i] = 0;
    __syncthreads();
    int E = sh_e;

    // ---- P1: per-block histogram ----
    int s = bid * chunk4, e = min(n4, s + chunk4);
    for (int i = s + t; i < e; i += 256) {
        int4 z = zone4[i];
        atomicAdd(&sh[z.x], 1); atomicAdd(&sh[z.y], 1);
        atomicAdd(&sh[z.z], 1); atomicAdd(&sh[z.w], 1);
    }
    __syncthreads();
    for (int i = t; i < N_DIST; i += 256)
        g_counts[i * NBIN + bid] = sh[i];
    grid_bar(0, E, t);

    // ---- P2: scan over blocks, 2 districts per block ----
    for (int dd = 0; dd < 2; dd++) {
        int d = bid * 2 + dd;
        int v0 = g_counts[d * NBIN + 2 * t];
        int v1 = g_counts[d * NBIN + 2 * t + 1];
        int ps = v0 + v1;
        int inc = ps;
        #pragma unroll
        for (int o = 1; o < 32; o <<= 1) {
            int u = __shfl_up_sync(0xffffffffu, inc, o);
            if (lane >= o) inc += u;
        }
        if (lane == 31) warp_part[w] = inc;
        __syncthreads();
        if (t == 0) {
            int run = 0;
            #pragma unroll
            for (int i = 0; i < 8; i++) { int v = warp_part[i]; warp_part[i] = run; run += v; }
        }
        __syncthreads();
        int epr = warp_part[w] + (inc - ps);
        g_bcursor[(2 * t) * N_DIST + d]     = epr;
        g_bcursor[(2 * t + 1) * N_DIST + d] = epr + v0;
        if (t == 255) g_total[d] = epr + ps;
        __syncthreads();
    }
    grid_bar(1, E, t);

    // ---- P3: district scan (block 0) ----
    if (bid == 0) {
        int4 tt = ((const int4*)g_total)[t];
        int mysum = tt.x + tt.y + tt.z + tt.w;
        int inc = mysum;
        #pragma unroll
        for (int o = 1; o < 32; o <<= 1) {
            int u = __shfl_up_sync(0xffffffffu, inc, o);
            if (lane >= o) inc += u;
        }
        if (lane == 31) warp_part[w] = inc;
        __syncthreads();
        if (t == 0) {
            int run = 0;
            #pragma unroll
            for (int i = 0; i < 8; i++) { int v = warp_part[i]; warp_part[i] = run; run += v; }
        }
        __syncthreads();
        int e0 = warp_part[w] + (inc - mysum);
        g_offsets[4 * t + 0] = e0;
        g_offsets[4 * t + 1] = e0 + tt.x;
        g_offsets[4 * t + 2] = e0 + tt.x + tt.y;
        g_offsets[4 * t + 3] = e0 + tt.x + tt.y + tt.z;
        if (t == 255) g_offsets[N_DIST] = e0 + mysum;
    }
    grid_bar(2, E, t);

    // ---- P4: scatter (smem atomics) ----
    int4 off = ((const int4*)g_offsets)[t];
    int4 bc  = ((const int4*)g_bcursor)[bid * (N_DIST / 4) + t];
    sh[4 * t + 0] = off.x + bc.x;
    sh[4 * t + 1] = off.y + bc.y;
    sh[4 * t + 2] = off.z + bc.z;
    sh[4 * t + 3] = off.w + bc.w;
    __syncthreads();
    for (int i = s + t; i < e; i += 256) {
        int4 z = zone4[i];
        int p0 = atomicAdd(&sh[z.x], 1);
        int p1 = atomicAdd(&sh[z.y], 1);
        int p2 = atomicAdd(&sh[z.z], 1);
        int p3 = atomicAdd(&sh[z.w], 1);
        int i0 = i * 4;
        g_order[p0] = i0;
        g_order[p1] = i0 + 1;
        g_order[p2] = i0 + 2;
        g_order[p3] = i0 + 3;
    }
}

// ================================================================ gather (split-2) + fused MLP
// 2048 blocks: district d = blockIdx>>1, half h = blockIdx&1. 256 threads = 8 warps.
__global__ void __launch_bounds__(256) k_gather(
    const float4* __restrict__ x4,
    const float* __restrict__ w1, const float* __restrict__ b1,
    const float* __restrict__ w2, const float* __restrict__ b2,
    float* __restrict__ out)
{
    __shared__ __align__(16) char smem_buf[12 * 1024];
    int*   sh_idx  = (int*)smem_buf;                                  // 8KB (gather)
    float4 (*sh_part)[32] = (float4(*)[32])(smem_buf + 8192);         // 4KB (gather)
    float  (*sh_head)[DIM] = (float(*)[DIM])smem_buf;                 // 4KB (mlp)
    float  (*sh_h1)[HID]   = (float(*)[HID])(smem_buf + 4096);        // 8KB (mlp)
    __shared__ int sh_tmp;

    int bid = blockIdx.x;
    int d = bid >> 1, h = bid & 1;
    int t = threadIdx.x;
    int w = t >> 5, lane = t & 31;

    if (t == 0) sh_tmp = *(volatile int*)&g_epoch;
    __syncthreads();
    int E = sh_tmp;

    int s0 = g_offsets[d], e0 = g_offsets[d + 1];
    int cnt0 = e0 - s0;
    int half = (cnt0 + 1) >> 1;
    int s = s0 + (h ? half : 0);
    int e = h ? e0 : (s0 + half);
    int cnt = e - s;
    float4 acc = make_float4(0.f, 0.f, 0.f, 0.f);

    for (int base = 0; base < cnt; base += GCHUNK) {
        int m = min(GCHUNK, cnt - base);
        __syncthreads();
        for (int i = t; i < m; i += 256)
            sh_idx[i] = g_order[s + base + i];
        __syncthreads();

        int r = w;
        for (; r + 64 <= m; r += 64) {       // 8 warps x 8-way unroll
            float4 v[8];
            #pragma unroll
            for (int u = 0; u < 8; u++) {
                size_t p = (size_t)sh_idx[r + u * 8] * 32 + lane;
                v[u] = __ldcs(&x4[p]);
            }
            #pragma unroll
            for (int u = 0; u < 8; u++) {
                acc.x += v[u].x; acc.y += v[u].y;
                acc.z += v[u].z; acc.w += v[u].w;
            }
        }
        for (; r < m; r += 8) {
            float4 v = __ldcs(&x4[(size_t)sh_idx[r] * 32 + lane]);
            acc.x += v.x; acc.y += v.y; acc.z += v.z; acc.w += v.w;
        }
    }

    sh_part[w][lane] = acc;
    __syncthreads();
    if (w == 0) {
        float4 r = sh_part[0][lane];
        #pragma unroll
        for (int wi = 1; wi < 8; wi++) {
            float4 p = sh_part[wi][lane];
            r.x += p.x; r.y += p.y; r.z += p.z; r.w += p.w;
        }
        ((float4*)g_heads[h])[d * 32 + lane] = r;   // partial, no ReLU yet
        __threadfence();
    }
    __syncthreads();

    int grp = d >> 3;
    if (t == 0) {
        int old = atomicAdd(&g_done[grp], 1);
        sh_tmp = (old == (E + 1) * 16 - 1) ? 1 : 0;
    }
    __syncthreads();
    if (!sh_tmp) return;
    __threadfence();

    // ---------------- fused MLP for this group's 8 districts ----------------
    int gbase = grp * 8;
    __syncthreads();   // smem reuse barrier
    for (int idx = t; idx < 8 * DIM; idx += 256) {
        float p = __ldcg(&g_heads[0][gbase * DIM + idx]) + __ldcg(&g_heads[1][gbase * DIM + idx]);
        sh_head[idx >> 7][idx & 127] = fmaxf(p, 0.f);
    }
    __syncthreads();

    {   // Phase A: h1 = relu(head @ w1 + b1), thread t = hidden column
        int col = t;
        float accm[8];
        float bb = b1[col];
        #pragma unroll
        for (int r = 0; r < 8; r++) accm[r] = bb;
        #pragma unroll 4
        for (int k = 0; k < DIM; k++) {
            float wv = w1[k * HID + col];
            #pragma unroll
            for (int r = 0; r < 8; r++) accm[r] += sh_head[r][k] * wv;
        }
        #pragma unroll
        for (int r = 0; r < 8; r++) sh_h1[r][col] = fmaxf(accm[r], 0.f);
    }
    __syncthreads();

    {   // Phase B: out = h1 @ w2 + b2
        int col = t & 127;
        int r0  = (t >> 7) * 4;
        float accm[4];
        float bb = b2[col];
        #pragma unroll
        for (int r = 0; r < 4; r++) accm[r] = bb;
        #pragma unroll 4
        for (int k = 0; k < HID; k++) {
            float wv = w2[k * DIM + col];
            #pragma unroll
            for (int r = 0; r < 4; r++) accm[r] += sh_h1[r0 + r][k] * wv;
        }
        #pragma unroll
        for (int r = 0; r < 4; r++)
            out[(size_t)(gbase + r0 + r) * DIM + col] = accm[r];
    }

    __threadfence();
    if (t == 0) {
        int old = atomicAdd(&g_grpdone, 1);
        if (old == (E + 1) * NGROUP - 1) atomicExch(&g_epoch, E + 1);
    }
}

// ---------------------------------------------------------------- launch
extern "C" void kernel_launch(void* const* d_in, const int* in_sizes, int n_in,
                              void* d_out, int out_size) {
    const float* x    = (const float*)d_in[0];
    const int*   zone = (const int*)d_in[1];
    const float* w1   = (const float*)d_in[2];
    const float* b1   = (const float*)d_in[3];
    const float* w2   = (const float*)d_in[4];
    const float* b2   = (const float*)d_in[5];
    float*       out  = (float*)d_out;
    int n  = in_sizes[1];                // 500000, divisible by 4
    int n4 = n / 4;
    int chunk4 = (n4 + NBIN - 1) / NBIN;

    k_bin   <<<NBIN, 256>>>((const int4*)zone, n4, chunk4);
    k_gather<<<N_DIST * 2, 256>>>((const float4*)x, w1, b1, w2, b2, out);
}

// round 15
// speedup vs baseline: 1.0473x; 1.0064x over previous
#include <cuda_runtime.h>
#include <cstdint>

#define N_DIST 1024
#define DIM    128
#define HID    256
#define MAXN   500000
#define NBIN   512
#define GCHUNK 2048
#define NGROUP (N_DIST / 8)

// Scratch (no allocations). All cross-launch counters are epoch-relative monotonic.
__device__ __align__(16) int g_counts[N_DIST * NBIN];   // [d][b]
__device__ __align__(16) int g_bcursor[NBIN * N_DIST];  // [b][d]
__device__ __align__(16) int g_total[N_DIST];
__device__ __align__(16) int g_offsets[N_DIST + 1];
__device__ int   g_order[MAXN];
__device__ float g_heads[2][N_DIST * DIM];
__device__ int   g_done[NGROUP];       // +16 per group per launch (monotonic)
__device__ int   g_bar[1];             // +NBIN per launch (monotonic)
__device__ int   g_grpdone;            // +NGROUP per launch (monotonic)
__device__ int   g_epoch;              // bumped once per launch by last MLP group

// ================================================================ binA: hist + scan_blocks (1 grid barrier)
__global__ void __launch_bounds__(256) k_binA(const int4* __restrict__ zone4, int n4, int chunk4) {
    __shared__ int sh[N_DIST];
    __shared__ int warp_part[8];
    __shared__ int sh_e;
    int bid = blockIdx.x, t = threadIdx.x;
    int lane = t & 31, w = t >> 5;

    if (t == 0) sh_e = *(volatile int*)&g_epoch;
    for (int i = t; i < N_DIST; i += 256) sh[i] = 0;
    __syncthreads();
    int E = sh_e;

    // ---- P1: per-block histogram ----
    int s = bid * chunk4, e = min(n4, s + chunk4);
    for (int i = s + t; i < e; i += 256) {
        int4 z = zone4[i];
        atomicAdd(&sh[z.x], 1); atomicAdd(&sh[z.y], 1);
        atomicAdd(&sh[z.z], 1); atomicAdd(&sh[z.w], 1);
    }
    __syncthreads();
    for (int i = t; i < N_DIST; i += 256)
        g_counts[i * NBIN + bid] = sh[i];

    // ---- grid barrier ----
    __syncthreads();
    if (t == 0) {
        __threadfence();
        atomicAdd(&g_bar[0], 1);
        while (*(volatile int*)&g_bar[0] < (E + 1) * NBIN) __nanosleep(64);
        __threadfence();
    }
    __syncthreads();

    // ---- P2: scan over blocks, 2 districts per block ----
    for (int dd = 0; dd < 2; dd++) {
        int d = bid * 2 + dd;
        int v0 = g_counts[d * NBIN + 2 * t];
        int v1 = g_counts[d * NBIN + 2 * t + 1];
        int ps = v0 + v1;
        int inc = ps;
        #pragma unroll
        for (int o = 1; o < 32; o <<= 1) {
            int u = __shfl_up_sync(0xffffffffu, inc, o);
            if (lane >= o) inc += u;
        }
        if (lane == 31) warp_part[w] = inc;
        __syncthreads();
        if (t == 0) {
            int run = 0;
            #pragma unroll
            for (int i = 0; i < 8; i++) { int v = warp_part[i]; warp_part[i] = run; run += v; }
        }
        __syncthreads();
        int epr = warp_part[w] + (inc - ps);
        g_bcursor[(2 * t) * N_DIST + d]     = epr;
        g_bcursor[(2 * t + 1) * N_DIST + d] = epr + v0;
        if (t == 255) g_total[d] = epr + ps;
        __syncthreads();
    }
}

// ================================================================ scatter (inline district scan + smem atomics)
__global__ void __launch_bounds__(256) k_scatter(const int4* __restrict__ zone4, int n4, int chunk4) {
    __shared__ int cur[N_DIST];
    __shared__ int warp_part[8];
    int b = blockIdx.x, t = threadIdx.x;
    int lane = t & 31, w = t >> 5;

    // --- inline exclusive scan of g_total (1024 elems, 4 per thread) ---
    int4 tt = ((const int4*)g_total)[t];
    int mysum = tt.x + tt.y + tt.z + tt.w;
    int inc = mysum;
    #pragma unroll
    for (int o = 1; o < 32; o <<= 1) {
        int v = __shfl_up_sync(0xffffffffu, inc, o);
        if (lane >= o) inc += v;
    }
    if (lane == 31) warp_part[w] = inc;
    __syncthreads();
    if (t == 0) {
        int run = 0;
        #pragma unroll
        for (int i = 0; i < 8; i++) { int v = warp_part[i]; warp_part[i] = run; run += v; }
    }
    __syncthreads();
    int e0 = warp_part[w] + (inc - mysum);
    int e1 = e0 + tt.x, e2 = e1 + tt.y, e3 = e2 + tt.z;

    if (b == 0) {                                 // publish offsets for gather
        g_offsets[4 * t + 0] = e0;
        g_offsets[4 * t + 1] = e1;
        g_offsets[4 * t + 2] = e2;
        g_offsets[4 * t + 3] = e3;
        if (t == 255) g_offsets[N_DIST] = e3 + tt.w;
    }

    int4 bc = ((const int4*)g_bcursor)[b * (N_DIST / 4) + t];   // coalesced
    cur[4 * t + 0] = e0 + bc.x;
    cur[4 * t + 1] = e1 + bc.y;
    cur[4 * t + 2] = e2 + bc.z;
    cur[4 * t + 3] = e3 + bc.w;
    __syncthreads();

    int s = b * chunk4, e = min(n4, s + chunk4);
    for (int i = s + t; i < e; i += 256) {
        int4 z = zone4[i];
        int p0 = atomicAdd(&cur[z.x], 1);
        int p1 = atomicAdd(&cur[z.y], 1);
        int p2 = atomicAdd(&cur[z.z], 1);
        int p3 = atomicAdd(&cur[z.w], 1);
        int i0 = i * 4;
        g_order[p0] = i0;
        g_order[p1] = i0 + 1;
        g_order[p2] = i0 + 2;
        g_order[p3] = i0 + 3;
    }
}

// ================================================================ gather (split-2) + fused MLP
// 2048 blocks: district d = blockIdx>>1, half h = blockIdx&1. 256 threads = 8 warps.
__global__ void __launch_bounds__(256) k_gather(
    const float4* __restrict__ x4,
    const float* __restrict__ w1, const float* __restrict__ b1,
    const float* __restrict__ w2, const float* __restrict__ b2,
    float* __restrict__ out)
{
    __shared__ __align__(16) char smem_buf[12 * 1024];
    int*   sh_idx  = (int*)smem_buf;                                  // 8KB (gather)
    float4 (*sh_part)[32] = (float4(*)[32])(smem_buf + 8192);         // 4KB (gather)
    float  (*sh_head)[DIM] = (float(*)[DIM])smem_buf;                 // 4KB (mlp)
    float  (*sh_h1)[HID]   = (float(*)[HID])(smem_buf + 4096);        // 8KB (mlp)
    __shared__ int sh_tmp;

    int bid = blockIdx.x;
    int d = bid >> 1, h = bid & 1;
    int t = threadIdx.x;
    int w = t >> 5, lane = t & 31;

    if (t == 0) sh_tmp = *(volatile int*)&g_epoch;
    __syncthreads();
    int E = sh_tmp;

    int s0 = g_offsets[d], e0 = g_offsets[d + 1];
    int cnt0 = e0 - s0;
    int half = (cnt0 + 1) >> 1;
    int s = s0 + (h ? half : 0);
    int e = h ? e0 : (s0 + half);
    int cnt = e - s;
    float4 acc = make_float4(0.f, 0.f, 0.f, 0.f);

    for (int base = 0; base < cnt; base += GCHUNK) {
        int m = min(GCHUNK, cnt - base);
        __syncthreads();
        for (int i = t; i < m; i += 256)
            sh_idx[i] = g_order[s + base + i];
        __syncthreads();

        int r = w;
        for (; r + 64 <= m; r += 64) {       // 8 warps x 8-way unroll
            float4 v[8];
            #pragma unroll
            for (int u = 0; u < 8; u++) {
                size_t p = (size_t)sh_idx[r + u * 8] * 32 + lane;
                v[u] = __ldcs(&x4[p]);
            }
            #pragma unroll
            for (int u = 0; u < 8; u++) {
                acc.x += v[u].x; acc.y += v[u].y;
                acc.z += v[u].z; acc.w += v[u].w;
            }
        }
        for (; r < m; r += 8) {
            float4 v = __ldcs(&x4[(size_t)sh_idx[r] * 32 + lane]);
            acc.x += v.x; acc.y += v.y; acc.z += v.z; acc.w += v.w;
        }
    }

    sh_part[w][lane] = acc;
    __syncthreads();
    if (w == 0) {
        float4 r = sh_part[0][lane];
        #pragma unroll
        for (int wi = 1; wi < 8; wi++) {
            float4 p = sh_part[wi][lane];
            r.x += p.x; r.y += p.y; r.z += p.z; r.w += p.w;
        }
        ((float4*)g_heads[h])[d * 32 + lane] = r;   // partial, no ReLU yet
        __threadfence();
    }
    __syncthreads();

    int grp = d >> 3;
    if (t == 0) {
        int old = atomicAdd(&g_done[grp], 1);
        sh_tmp = (old == (E + 1) * 16 - 1) ? 1 : 0;
    }
    __syncthreads();
    if (!sh_tmp) return;
    __threadfence();

    // ---------------- fused MLP for this group's 8 districts ----------------
    int gbase = grp * 8;
    __syncthreads();   // smem reuse barrier
    for (int idx = t; idx < 8 * DIM; idx += 256) {
        float p = __ldcg(&g_heads[0][gbase * DIM + idx]) + __ldcg(&g_heads[1][gbase * DIM + idx]);
        sh_head[idx >> 7][idx & 127] = fmaxf(p, 0.f);
    }
    __syncthreads();

    {   // Phase A: h1 = relu(head @ w1 + b1), thread t = hidden column
        int col = t;
        float accm[8];
        float bb = b1[col];
        #pragma unroll
        for (int r = 0; r < 8; r++) accm[r] = bb;
        #pragma unroll 4
        for (int k = 0; k < DIM; k++) {
            float wv = w1[k * HID + col];
            #pragma unroll
            for (int r = 0; r < 8; r++) accm[r] += sh_head[r][k] * wv;
        }
        #pragma unroll
        for (int r = 0; r < 8; r++) sh_h1[r][col] = fmaxf(accm[r], 0.f);
    }
    __syncthreads();

    {   // Phase B: out = h1 @ w2 + b2
        int col = t & 127;
        int r0  = (t >> 7) * 4;
        float accm[4];
        float bb = b2[col];
        #pragma unroll
        for (int r = 0; r < 4; r++) accm[r] = bb;
        #pragma unroll 4
        for (int k = 0; k < HID; k++) {
            float wv = w2[k * DIM + col];
            #pragma unroll
            for (int r = 0; r < 4; r++) accm[r] += sh_h1[r0 + r][k] * wv;
        }
        #pragma unroll
        for (int r = 0; r < 4; r++)
            out[(size_t)(gbase + r0 + r) * DIM + col] = accm[r];
    }

    __threadfence();
    if (t == 0) {
        int old = atomicAdd(&g_grpdone, 1);
        if (old == (E + 1) * NGROUP - 1) atomicExch(&g_epoch, E + 1);
    }
}

// ---------------------------------------------------------------- launch
extern "C" void kernel_launch(void* const* d_in, const int* in_sizes, int n_in,
                              void* d_out, int out_size) {
    const float* x    = (const float*)d_in[0];
    const int*   zone = (const int*)d_in[1];
    const float* w1   = (const float*)d_in[2];
    const float* b1   = (const float*)d_in[3];
    const float* w2   = (const float*)d_in[4];
    const float* b2   = (const float*)d_in[5];
    float*       out  = (float*)d_out;
    int n  = in_sizes[1];                // 500000, divisible by 4
    int n4 = n / 4;
    int chunk4 = (n4 + NBIN - 1) / NBIN;

    k_binA  <<<NBIN, 256>>>((const int4*)zone, n4, chunk4);
    k_scatter<<<NBIN, 256>>>((const int4*)zone, n4, chunk4);
    k_gather<<<N_DIST * 2, 256>>>((const float4*)x, w1, b1, w2, b2, out);
}